// round 14
// baseline (speedup 1.0000x reference)
#include <cuda_runtime.h>
#include <cstdint>
#include <cstddef>

#define TN      16
#define MP      8
#define DD      256
#define HH      256
#define NTOT    100000
#define THREADS 256
#define G       5                 // tiles per CTA  (6250 = 1250 * 5)

// ---- SMEM layout (float-unit offsets) ----
#define ACH   2576                // floats per A chunk: 128 rows * 20 + 16 pad (644 f4, %8==4)
#define F_A   0                   // 16 chunks, single buffer = 41216 floats
#define F_B   (16 * ACH)          // 41216 ; 2 buffers of [256][20]
#define BBUF  (256 * 20)          // 5120
#define F_TGT (F_B + 2 * BBUF)    // 51456 ; tgt [16][260]
#define TGS   260
#define F_BIAS (F_TGT + 16 * TGS) // 55616
#define F_NODE (F_BIAS + 256)     // 55872 (16 ints)
#define F_TNSQ (F_NODE + 16)      // 55888
#define F_TNRM (F_TNSQ + 256)     // 56144
#define F_REDD (F_TNRM + 16)      // 56160
#define F_REDN (F_REDD + 256)     // 56416
#define F_COS  (F_REDN + 256)     // 56672
#define F_ATT  (F_COS + 128)      // 56800
#define F_END  (F_ATT + 128)      // 56928
#define SMEM_REQ (F_END * 4)      // 227712 bytes

// ---------------- PTX helpers ----------------
__device__ __forceinline__ uint32_t smem_u32(const void* p) {
    uint32_t a;
    asm("{ .reg .u64 t; cvta.to.shared.u64 t, %1; cvt.u32.u64 %0, t; }" : "=r"(a) : "l"(p));
    return a;
}
__device__ __forceinline__ void cp16(uint32_t dst, const void* src) {
    asm volatile("cp.async.cg.shared.global [%0], [%1], 16;" :: "r"(dst), "l"(src));
}
__device__ __forceinline__ void cp_commit() {
    asm volatile("cp.async.commit_group;" ::: "memory");
}
template <int N>
__device__ __forceinline__ void cp_wait() {
    asm volatile("cp.async.wait_group %0;" :: "n"(N) : "memory");
}
__device__ __forceinline__ void mma_tf32(float& d0, float& d1, float& d2, float& d3,
                                         uint32_t a0, uint32_t a1, uint32_t a2, uint32_t a3,
                                         uint32_t b0, uint32_t b1) {
    asm volatile(
        "mma.sync.aligned.m16n8k8.row.col.f32.tf32.tf32.f32 "
        "{%0,%1,%2,%3}, {%4,%5,%6,%7}, {%8,%9}, {%0,%1,%2,%3};"
        : "+f"(d0), "+f"(d1), "+f"(d2), "+f"(d3)
        : "r"(a0), "r"(a1), "r"(a2), "r"(a3), "r"(b0), "r"(b1));
}
__device__ __forceinline__ float tanh_fast(float x) {
    float r; asm("tanh.approx.f32 %0, %1;" : "=f"(r) : "f"(x)); return r;
}

// ---------------- staging helpers ----------------
// One A chunk (16 k-cols, 512 float4) of the tile at node base n0t.
__device__ __forceinline__ void stage_A_chunk(uint32_t sb, int ch,
                                              const float* __restrict__ homo,
                                              int n0t, int tid) {
    #pragma unroll
    for (int q = 0; q < 2; q++) {
        int i = q * THREADS + tid;          // 0..511
        int r = i >> 2, fl = i & 3;         // GEMM row, float4-in-chunk
        int m = r >> 4, j = r & 15;
        cp16(sb + (uint32_t)(F_A + ch * ACH + r * 20 + fl * 4) * 4,
             homo + ((size_t)m * NTOT + n0t + j) * DD + ch * 16 + fl * 4);
    }
}
__device__ __forceinline__ void stage_B(uint32_t sb, int c,
                                        const float* __restrict__ Wg, int tid) {
    int bbase = F_B + (c & 1) * BBUF;
    #pragma unroll
    for (int q = 0; q < 4; q++)
        cp16(sb + (uint32_t)(bbase + tid * 20 + q * 4) * 4,
             Wg + (size_t)tid * DD + c * 16 + q * 4);
}
__device__ __forceinline__ void stage_tgt(uint32_t sb, const int* __restrict__ sN,
                                          const float* __restrict__ outemb, int tid) {
    #pragma unroll
    for (int q = 0; q < 4; q++) {
        int i = q * THREADS + tid;
        int j = i >> 6, f4 = i & 63;
        cp16(sb + (uint32_t)(F_TGT + j * TGS + f4 * 4) * 4,
             outemb + (size_t)sN[j] * HH + f4 * 4);
    }
}

// ---------------- kernel ----------------
__global__ void __launch_bounds__(THREADS, 1)
hete_attn_kernel(const int* __restrict__ nodes,
                 const float* __restrict__ homo,
                 const float* __restrict__ Wg,
                 const float* __restrict__ bg,
                 const float* __restrict__ outemb,
                 float* __restrict__ outp)
{
    extern __shared__ float s[];
    const uint32_t sb = smem_u32(s);
    const int tid  = threadIdx.x;
    const int wid  = tid >> 5;
    const int lane = tid & 31;
    const int wm   = wid & 3;        // M-tile (rows wm*32..+32)
    const int wn   = wid >> 2;       // N-tile (cols wn*128..+128)
    const int g    = lane >> 2;      // 0..7
    const int l3   = lane & 3;       // 0..3
    const int tile0 = blockIdx.x * G;

    const uint32_t* Au = (const uint32_t*)s;
    int* sN = (int*)s + F_NODE;

    // ---- prologue (once per CTA) ----
    s[F_BIAS + tid] = bg[tid];
    if (tid < TN) sN[tid] = nodes[tile0 * TN + tid];
    stage_B(sb, 0, Wg, tid);
    stage_B(sb, 1, Wg, tid);
    cp_commit();                                     // GB
    #pragma unroll
    for (int ch = 0; ch < 3; ch++)
        stage_A_chunk(sb, ch, homo, tile0 * TN, tid);
    cp_commit();                                     // GA0

    for (int t = 0; t < G; t++) {
        const int n0t = (tile0 + t) * TN;

        float acc[2][16][4];
        #pragma unroll
        for (int ms = 0; ms < 2; ms++)
            #pragma unroll
            for (int nt = 0; nt < 16; nt++)
                #pragma unroll
                for (int e = 0; e < 4; e++) acc[ms][nt][e] = 0.f;

        // ---- mainloop: 16 K-chunks; B double-buffered; A streamed chunk-wise ----
        for (int i = 0; i < 16; i++) {
            if (i == 0 || i == 15) { cp_wait<0>(); __syncthreads(); }
            else if (i >= 2)       { cp_wait<1>(); __syncthreads(); }
            const int ab = i * ACH;                  // F_A == 0
            const int bb = F_B + (i & 1) * BBUF;
            #pragma unroll
            for (int ks = 0; ks < 2; ks++) {
                const int kg = ks * 8 + l3;
                uint32_t a0[2], a1[2], a2[2], a3[2];
                #pragma unroll
                for (int ms = 0; ms < 2; ms++) {
                    int r = wm * 32 + ms * 16 + g;
                    a0[ms] = Au[ab + r * 20 + kg];
                    a1[ms] = Au[ab + (r + 8) * 20 + kg];
                    a2[ms] = Au[ab + r * 20 + kg + 4];
                    a3[ms] = Au[ab + (r + 8) * 20 + kg + 4];
                }
                #pragma unroll
                for (int nt = 0; nt < 16; nt++) {
                    int n = wn * 128 + nt * 8 + g;
                    uint32_t b0 = Au[bb + n * 20 + kg];
                    uint32_t b1 = Au[bb + n * 20 + kg + 4];
                    #pragma unroll
                    for (int ms = 0; ms < 2; ms++)
                        mma_tf32(acc[ms][nt][0], acc[ms][nt][1],
                                 acc[ms][nt][2], acc[ms][nt][3],
                                 a0[ms], a1[ms], a2[ms], a3[ms], b0, b1);
                }
            }
            __syncthreads();                         // B buf (i&1) free; A ch i consumed
            bool commit = false;
            if (i <= 13) { stage_B(sb, i + 2, Wg, tid); commit = true; }
            if (i <= 12) { stage_A_chunk(sb, i + 3, homo, n0t, tid); commit = true; }
            if (i == 0)  { stage_tgt(sb, sN, outemb, tid); commit = true; }
            if (commit) cp_commit();                 // G_i  (i = 0..13)
        }

        // ---- epilogue tile t ----
        if (t + 1 < G) {                             // B0/B1 for next tile (bufs free)
            stage_B(sb, 0, Wg, tid);
            stage_B(sb, 1, Wg, tid);
            cp_commit();                             // GB(t+1)
        }
        const float* tg = s + F_TGT;
        {   // partial ||tgt||^2
            int j = tid >> 4, seg = tid & 15;
            float a0 = 0.f;
            #pragma unroll
            for (int e = 0; e < 16; e++) {
                float v = tg[j * TGS + seg * 16 + e];
                a0 += v * v;
            }
            s[F_TNSQ + seg * 16 + j] = a0;
        }
        {   // tanh + dot/norm from register accumulators
            float dot[2][2] = {{0.f, 0.f}, {0.f, 0.f}};
            float nrm[2][2] = {{0.f, 0.f}, {0.f, 0.f}};
            #pragma unroll
            for (int nt = 0; nt < 16; nt++) {
                int nc = wn * 128 + nt * 8 + 2 * l3;
                float bias0 = s[F_BIAS + nc];
                float bias1 = s[F_BIAS + nc + 1];
                float t0a = tg[g * TGS + nc];
                float t1a = tg[g * TGS + nc + 1];
                float t0b = tg[(g + 8) * TGS + nc];
                float t1b = tg[(g + 8) * TGS + nc + 1];
                #pragma unroll
                for (int ms = 0; ms < 2; ms++) {
                    float h0 = tanh_fast(acc[ms][nt][0] + bias0);
                    float h1 = tanh_fast(acc[ms][nt][1] + bias1);
                    float h2 = tanh_fast(acc[ms][nt][2] + bias0);
                    float h3 = tanh_fast(acc[ms][nt][3] + bias1);
                    dot[ms][0] += h0 * t0a + h1 * t1a;
                    nrm[ms][0] += h0 * h0 + h1 * h1;
                    dot[ms][1] += h2 * t0b + h3 * t1b;
                    nrm[ms][1] += h2 * h2 + h3 * h3;
                }
            }
            #pragma unroll
            for (int ms = 0; ms < 2; ms++)
                #pragma unroll
                for (int s1 = 0; s1 < 2; s1++) {
                    float d = dot[ms][s1], q = nrm[ms][s1];
                    d += __shfl_xor_sync(0xFFFFFFFF, d, 1);
                    d += __shfl_xor_sync(0xFFFFFFFF, d, 2);
                    q += __shfl_xor_sync(0xFFFFFFFF, q, 1);
                    q += __shfl_xor_sync(0xFFFFFFFF, q, 2);
                    if (l3 == 0) {
                        int m = wm * 2 + ms, j = g + s1 * 8;
                        s[F_REDD + wn * 128 + m * 16 + j] = d;
                        s[F_REDN + wn * 128 + m * 16 + j] = q;
                    }
                }
        }
        if (tid < 16) {                              // finalize ||tgt||
            float sum = 0.f;
            #pragma unroll
            for (int e = 0; e < 16; e++) sum += s[F_TNSQ + e * 16 + tid];
            s[F_TNRM + tid] = fmaxf(sqrtf(sum), 1e-8f);
        }
        __syncthreads();

        if (tid < 128) {                             // cosine per (m, j)
            float d = s[F_REDD + tid] + s[F_REDD + 128 + tid];
            float q = s[F_REDN + tid] + s[F_REDN + 128 + tid];
            float hn = fmaxf(sqrtf(q), 1e-8f);
            s[F_COS + tid] = d / (hn * s[F_TNRM + (tid & 15)]);
        }
        __syncthreads();

        if (tid < 16) {                              // softmax over 8 meta-paths
            float cv[MP], mx = -1e30f;
            #pragma unroll
            for (int m = 0; m < MP; m++) { cv[m] = s[F_COS + m * 16 + tid]; mx = fmaxf(mx, cv[m]); }
            float sum = 0.f;
            #pragma unroll
            for (int m = 0; m < MP; m++) { cv[m] = __expf(cv[m] - mx); sum += cv[m]; }
            float inv = 1.f / sum;
            #pragma unroll
            for (int m = 0; m < MP; m++) s[F_ATT + m * 16 + tid] = cv[m] * inv;
        }
        __syncthreads();

        {   // final weighted sum from the resident raw-fp32 A tile (chunked layout)
            int j = tid >> 4, q = tid & 15;          // 16 threads per node
            float a[MP];
            #pragma unroll
            for (int m = 0; m < MP; m++) a[m] = s[F_ATT + m * 16 + j];
            const float4* A4 = (const float4*)s;
            float4* orow = (float4*)(outp + (size_t)(n0t + j) * DD);
            #pragma unroll
            for (int sQ = 0; sQ < 4; sQ++) {
                int k4 = q + sQ * 16;                // 0..63
                int ch = k4 >> 2, in4 = k4 & 3;
                float4 accv = make_float4(0.f, 0.f, 0.f, 0.f);
                #pragma unroll
                for (int m = 0; m < MP; m++) {
                    float4 v = A4[ch * (ACH / 4) + (m * 16 + j) * 5 + in4];
                    accv.x += a[m] * v.x; accv.y += a[m] * v.y;
                    accv.z += a[m] * v.z; accv.w += a[m] * v.w;
                }
                orow[k4] = accv;
            }
        }

        __syncthreads();                             // A(t) reads done; safe to overwrite
        if (t + 1 < G) {                             // A ch0..2 + nodes for next tile
            #pragma unroll
            for (int ch = 0; ch < 3; ch++)
                stage_A_chunk(sb, ch, homo, n0t + TN, tid);
            cp_commit();                             // GA0(t+1)
            if (tid < TN) sN[tid] = nodes[(tile0 + t + 1) * TN + tid];
        }
    }
}

// ---------------- launch ----------------
extern "C" void kernel_launch(void* const* d_in, const int* in_sizes, int n_in,
                              void* d_out, int out_size) {
    const int* nodes = nullptr;
    const float *homo = nullptr, *W = nullptr, *b = nullptr, *emb = nullptr;
    for (int i = 0; i < n_in; i++) {
        switch (in_sizes[i]) {
            case 100000:    nodes = (const int*)d_in[i];   break;  // nodes [N]
            case 204800000: homo  = (const float*)d_in[i]; break;  // homo  [M,N,D]
            case 65536:     W     = (const float*)d_in[i]; break;  // W     [H,D]
            case 256:       b     = (const float*)d_in[i]; break;  // b     [H]
            case 51200000:  emb   = (const float*)d_in[i]; break;  // out_embedding
        }
    }
    cudaFuncSetAttribute(hete_attn_kernel,
                         cudaFuncAttributeMaxDynamicSharedMemorySize, SMEM_REQ);
    hete_attn_kernel<<<NTOT / (TN * G), THREADS, SMEM_REQ>>>(nodes, homo, W, b, emb, (float*)d_out);
}

// round 15
// speedup vs baseline: 1.0608x; 1.0608x over previous
#include <cuda_runtime.h>
#include <cuda_bf16.h>
#include <cstdint>
#include <cstddef>

#define TN      16
#define MP      8
#define DD      256
#define HH      256
#define NTOT    100000
#define THREADS 256
#define G       5                 // tiles per CTA  (6250 = 1250 * 5)
#define WS      264               // bf16 row stride for Wb / Ab (132 words ≡ 4 mod 32)
#define WSW     (WS / 2)          // 132 words
#define TGS     260               // fp32 stride for tgt

// SMEM (bytes): Wb 135168 + Ab 67584 + tg 16640 + bias 1024 + tnsq 1024
//             + tnrm 64 + redd 1024 + redn 1024 + cos 512 + att 512 = 224576
#define SMEM_REQ 224576

// ---------------- PTX helpers ----------------
__device__ __forceinline__ uint32_t smem_u32(const void* p) {
    uint32_t a;
    asm("{ .reg .u64 t; cvta.to.shared.u64 t, %1; cvt.u32.u64 %0, t; }" : "=r"(a) : "l"(p));
    return a;
}
__device__ __forceinline__ void cp16(uint32_t dst, const void* src) {
    asm volatile("cp.async.cg.shared.global [%0], [%1], 16;" :: "r"(dst), "l"(src));
}
__device__ __forceinline__ void cp_commit() {
    asm volatile("cp.async.commit_group;" ::: "memory");
}
template <int N>
__device__ __forceinline__ void cp_wait() {
    asm volatile("cp.async.wait_group %0;" :: "n"(N) : "memory");
}
// pack two fp32 -> bf16x2 (lo = first arg)
__device__ __forceinline__ uint32_t bf2(float lo, float hi) {
    uint32_t r;
    asm("cvt.rn.bf16x2.f32 %0, %1, %2;" : "=r"(r) : "f"(hi), "f"(lo));
    return r;
}
__device__ __forceinline__ void mma_bf16(float& d0, float& d1, float& d2, float& d3,
                                         uint32_t a0, uint32_t a1, uint32_t a2, uint32_t a3,
                                         uint32_t b0, uint32_t b1) {
    asm volatile(
        "mma.sync.aligned.m16n8k16.row.col.f32.bf16.bf16.f32 "
        "{%0,%1,%2,%3}, {%4,%5,%6,%7}, {%8,%9}, {%0,%1,%2,%3};"
        : "+f"(d0), "+f"(d1), "+f"(d2), "+f"(d3)
        : "r"(a0), "r"(a1), "r"(a2), "r"(a3), "r"(b0), "r"(b1));
}
__device__ __forceinline__ float tanh_fast(float x) {
    float r; asm("tanh.approx.f32 %0, %1;" : "=f"(r) : "f"(x)); return r;
}

// ---------------- A tile fp32 -> bf16 SMEM convert (coalesced, STS.64) ----------
__device__ __forceinline__ void convert_A(uint32_t* Abw, const float* __restrict__ homo,
                                          int n0t, int tid) {
    #pragma unroll 4
    for (int i = 0; i < 32; i++) {
        int idx = i * THREADS + tid;            // 0..8191
        int r = idx >> 6, f4 = idx & 63;        // GEMM row, float4 idx in row
        int m = r >> 4, j = r & 15;
        float4 v = __ldg((const float4*)(homo + ((size_t)m * NTOT + n0t + j) * DD) + f4);
        uint2 p = make_uint2(bf2(v.x, v.y), bf2(v.z, v.w));
        *(uint2*)(Abw + r * WSW + f4 * 2) = p;  // byte addr r*528+f4*8, 8-aligned
    }
}

// ---------------- kernel ----------------
__global__ void __launch_bounds__(THREADS, 1)
hete_attn_kernel(const int* __restrict__ nodes,
                 const float* __restrict__ homo,
                 const float* __restrict__ Wg,
                 const float* __restrict__ bg,
                 const float* __restrict__ outemb,
                 float* __restrict__ outp)
{
    extern __shared__ char smraw[];
    __nv_bfloat16* Wb = (__nv_bfloat16*)smraw;          // [256][264] bf16
    __nv_bfloat16* Ab = Wb + 256 * WS;                  // [128][264] bf16
    float* tg   = (float*)(Ab + 128 * WS);              // [16][260] fp32
    float* bias = tg + 16 * TGS;                        // [256]
    float* tnsq = bias + 256;                           // [16 seg][16 j]
    float* tnrm = tnsq + 256;                           // [16]
    float* redd = tnrm + 16;                            // [2 wn][8 m][16 j]
    float* redn = redd + 256;
    float* cosb = redn + 256;                           // [128]
    float* attb = cosb + 128;                           // [128]

    uint32_t* Wbw = (uint32_t*)Wb;
    uint32_t* Abw = (uint32_t*)Ab;
    const uint32_t tg_sb = smem_u32(tg);

    const int tid  = threadIdx.x;
    const int wid  = tid >> 5;
    const int lane = tid & 31;
    const int wm   = wid & 3;        // M-tile (rows wm*32..+32)
    const int wn   = wid >> 2;       // N-tile (cols wn*128..+128)
    const int g    = lane >> 2;      // 0..7
    const int l3   = lane & 3;       // 0..3
    const int tile0 = blockIdx.x * G;

    // ---- prologue (once per CTA): bias, W fp32->bf16, A(0) fp32->bf16 ----
    bias[tid] = bg[tid];
    #pragma unroll
    for (int q = 0; q < 4; q++) {                        // W: 256 rows, 4 thr/row
        int idx = q * THREADS + tid;
        int h = idx >> 2, part = idx & 3;                // part covers 16 float4
        const float4* src = (const float4*)(Wg + (size_t)h * DD) + part * 16;
        uint32_t* dst = Wbw + h * WSW + part * 32;
        #pragma unroll
        for (int f = 0; f < 16; f++) {
            float4 v = __ldg(&src[f]);
            dst[2 * f]     = bf2(v.x, v.y);
            dst[2 * f + 1] = bf2(v.z, v.w);
        }
    }
    convert_A(Abw, homo, tile0 * TN, tid);
    __syncthreads();

    for (int t = 0; t < G; t++) {
        const int n0t = (tile0 + t) * TN;

        // stage tgt(t) via cp.async (hidden behind mainloop)
        #pragma unroll
        for (int q = 0; q < 4; q++) {
            int i = q * THREADS + tid;
            int j = i >> 6, f4 = i & 63;
            int nd = __ldg(&nodes[n0t + j]);
            cp16(tg_sb + (uint32_t)(j * TGS + f4 * 4) * 4,
                 outemb + (size_t)nd * HH + f4 * 4);
        }
        cp_commit();

        float acc[2][16][4];
        #pragma unroll
        for (int ms = 0; ms < 2; ms++)
            #pragma unroll
            for (int nt = 0; nt < 16; nt++)
                #pragma unroll
                for (int e = 0; e < 4; e++) acc[ms][nt][e] = 0.f;

        // ---- mainloop: 16 x k16 bf16 MMA, zero syncs, zero staging ----
        const uint32_t* Arow0 = Abw + (wm * 32 + g) * WSW;
        const uint32_t* Brow0 = Wbw + (wn * 128 + g) * WSW;
        #pragma unroll 2
        for (int ks = 0; ks < 16; ks++) {
            const int kw = ks * 8 + l3;                  // word offset in row
            uint32_t a0[2], a1[2], a2[2], a3[2];
            #pragma unroll
            for (int ms = 0; ms < 2; ms++) {
                const uint32_t* ar = Arow0 + ms * 16 * WSW;
                a0[ms] = ar[kw];
                a1[ms] = ar[8 * WSW + kw];
                a2[ms] = ar[kw + 4];
                a3[ms] = ar[8 * WSW + kw + 4];
            }
            #pragma unroll
            for (int nt = 0; nt < 16; nt++) {
                uint32_t b0 = Brow0[nt * 8 * WSW + kw];
                uint32_t b1 = Brow0[nt * 8 * WSW + kw + 4];
                #pragma unroll
                for (int ms = 0; ms < 2; ms++)
                    mma_bf16(acc[ms][nt][0], acc[ms][nt][1],
                             acc[ms][nt][2], acc[ms][nt][3],
                             a0[ms], a1[ms], a2[ms], a3[ms], b0, b1);
            }
        }
        cp_wait<0>();
        __syncthreads();                                 // tgt ready; all MMA done

        // ---- epilogue ----
        {   // partial ||tgt||^2
            int j = tid >> 4, seg = tid & 15;
            float a0 = 0.f;
            #pragma unroll
            for (int e = 0; e < 16; e++) {
                float v = tg[j * TGS + seg * 16 + e];
                a0 += v * v;
            }
            tnsq[seg * 16 + j] = a0;
        }
        {   // tanh + dot/norm from register accumulators
            float dot[2][2] = {{0.f, 0.f}, {0.f, 0.f}};
            float nrm[2][2] = {{0.f, 0.f}, {0.f, 0.f}};
            #pragma unroll
            for (int nt = 0; nt < 16; nt++) {
                int nc = wn * 128 + nt * 8 + 2 * l3;
                float bias0 = bias[nc];
                float bias1 = bias[nc + 1];
                float t0a = tg[g * TGS + nc];
                float t1a = tg[g * TGS + nc + 1];
                float t0b = tg[(g + 8) * TGS + nc];
                float t1b = tg[(g + 8) * TGS + nc + 1];
                #pragma unroll
                for (int ms = 0; ms < 2; ms++) {
                    float h0 = tanh_fast(acc[ms][nt][0] + bias0);
                    float h1 = tanh_fast(acc[ms][nt][1] + bias1);
                    float h2 = tanh_fast(acc[ms][nt][2] + bias0);
                    float h3 = tanh_fast(acc[ms][nt][3] + bias1);
                    dot[ms][0] += h0 * t0a + h1 * t1a;
                    nrm[ms][0] += h0 * h0 + h1 * h1;
                    dot[ms][1] += h2 * t0b + h3 * t1b;
                    nrm[ms][1] += h2 * h2 + h3 * h3;
                }
            }
            #pragma unroll
            for (int ms = 0; ms < 2; ms++)
                #pragma unroll
                for (int s1 = 0; s1 < 2; s1++) {
                    float d = dot[ms][s1], q = nrm[ms][s1];
                    d += __shfl_xor_sync(0xFFFFFFFF, d, 1);
                    d += __shfl_xor_sync(0xFFFFFFFF, d, 2);
                    q += __shfl_xor_sync(0xFFFFFFFF, q, 1);
                    q += __shfl_xor_sync(0xFFFFFFFF, q, 2);
                    if (l3 == 0) {
                        int m = wm * 2 + ms, j = g + s1 * 8;
                        redd[wn * 128 + m * 16 + j] = d;
                        redn[wn * 128 + m * 16 + j] = q;
                    }
                }
        }
        __syncthreads();

        if (tid < 16) {                                  // finalize ||tgt||
            float sum = 0.f;
            #pragma unroll
            for (int e = 0; e < 16; e++) sum += tnsq[e * 16 + tid];
            tnrm[tid] = fmaxf(sqrtf(sum), 1e-8f);
        }
        if (t + 1 < G)                                   // A(t+1): Ab is dead now
            convert_A(Abw, homo, n0t + TN, tid);
        __syncthreads();

        if (tid < 128) {                                 // cosine per (m, j)
            float d = redd[tid] + redd[128 + tid];
            float q = redn[tid] + redn[128 + tid];
            float hn = fmaxf(sqrtf(q), 1e-8f);
            cosb[tid] = d / (hn * tnrm[tid & 15]);
        }
        __syncthreads();

        if (tid < 16) {                                  // softmax over 8 meta-paths
            float cv[MP], mx = -1e30f;
            #pragma unroll
            for (int m = 0; m < MP; m++) { cv[m] = cosb[m * 16 + tid]; mx = fmaxf(mx, cv[m]); }
            float sum = 0.f;
            #pragma unroll
            for (int m = 0; m < MP; m++) { cv[m] = __expf(cv[m] - mx); sum += cv[m]; }
            float inv = 1.f / sum;
            #pragma unroll
            for (int m = 0; m < MP; m++) attb[m * 16 + tid] = cv[m] * inv;
        }
        __syncthreads();

        {   // final weighted sum: exact fp32, homo re-read from L2
            int j = tid >> 4, q = tid & 15;              // 16 threads per node
            float a[MP];
            #pragma unroll
            for (int m = 0; m < MP; m++) a[m] = attb[m * 16 + j];
            float4* orow = (float4*)(outp + (size_t)(n0t + j) * DD);
            #pragma unroll
            for (int sQ = 0; sQ < 4; sQ++) {
                int k4 = q + sQ * 16;                    // 0..63
                float4 accv = make_float4(0.f, 0.f, 0.f, 0.f);
                #pragma unroll
                for (int m = 0; m < MP; m++) {
                    float4 v = __ldg((const float4*)(homo +
                               ((size_t)m * NTOT + n0t + j) * DD) + k4);
                    accv.x += a[m] * v.x; accv.y += a[m] * v.y;
                    accv.z += a[m] * v.z; accv.w += a[m] * v.w;
                }
                orow[k4] = accv;
            }
        }
        // no trailing sync needed: next tile's post-mainloop barrier orders all
        // SMEM rewrites (tg via cp.async is the only pre-barrier write, and the
        // weighted sum does not read tg).
    }
}

// ---------------- launch ----------------
extern "C" void kernel_launch(void* const* d_in, const int* in_sizes, int n_in,
                              void* d_out, int out_size) {
    const int* nodes = nullptr;
    const float *homo = nullptr, *W = nullptr, *b = nullptr, *emb = nullptr;
    for (int i = 0; i < n_in; i++) {
        switch (in_sizes[i]) {
            case 100000:    nodes = (const int*)d_in[i];   break;  // nodes [N]
            case 204800000: homo  = (const float*)d_in[i]; break;  // homo  [M,N,D]
            case 65536:     W     = (const float*)d_in[i]; break;  // W     [H,D]
            case 256:       b     = (const float*)d_in[i]; break;  // b     [H]
            case 51200000:  emb   = (const float*)d_in[i]; break;  // out_embedding
        }
    }
    cudaFuncSetAttribute(hete_attn_kernel,
                         cudaFuncAttributeMaxDynamicSharedMemorySize, SMEM_REQ);
    hete_attn_kernel<<<NTOT / (TN * G), THREADS, SMEM_REQ>>>(nodes, homo, W, b, emb, (float*)d_out);
}

// round 16
// speedup vs baseline: 1.1949x; 1.1264x over previous
#include <cuda_runtime.h>
#include <cuda_bf16.h>
#include <cstdint>
#include <cstddef>

#define TN      16
#define MP      8
#define DD      256
#define HH      256
#define NTOT    100000
#define THREADS 256
#define G       5                 // tiles per CTA  (6250 = 1250 * 5)
#define WS      264               // bf16 row stride for Wb / Ab (528 B)
#define WSW     (WS / 2)          // 132 words
#define WSB     (WS * 2)          // 528 bytes
#define TGS     260               // fp32 stride for tgt

// SMEM (bytes): Wb 135168 + Ab 67584 + tg 16640 + bias 1024 + tnsq 1024
//             + tnrm 64 + redd 1024 + redn 1024 + cos 512 + att 512 = 224576
#define SMEM_REQ 224576

// ---------------- PTX helpers ----------------
__device__ __forceinline__ uint32_t smem_u32(const void* p) {
    uint32_t a;
    asm("{ .reg .u64 t; cvta.to.shared.u64 t, %1; cvt.u32.u64 %0, t; }" : "=r"(a) : "l"(p));
    return a;
}
__device__ __forceinline__ void cp16(uint32_t dst, const void* src) {
    asm volatile("cp.async.cg.shared.global [%0], [%1], 16;" :: "r"(dst), "l"(src));
}
__device__ __forceinline__ void cp_commit() {
    asm volatile("cp.async.commit_group;" ::: "memory");
}
template <int N>
__device__ __forceinline__ void cp_wait() {
    asm volatile("cp.async.wait_group %0;" :: "n"(N) : "memory");
}
__device__ __forceinline__ uint32_t bf2(float lo, float hi) {
    uint32_t r;
    asm("cvt.rn.bf16x2.f32 %0, %1, %2;" : "=r"(r) : "f"(hi), "f"(lo));
    return r;
}
__device__ __forceinline__ void ldsm4(uint32_t& r0, uint32_t& r1, uint32_t& r2, uint32_t& r3,
                                      uint32_t addr) {
    asm volatile("ldmatrix.sync.aligned.m8n8.x4.shared.b16 {%0,%1,%2,%3}, [%4];"
                 : "=r"(r0), "=r"(r1), "=r"(r2), "=r"(r3) : "r"(addr));
}
__device__ __forceinline__ void mma_bf16(float& d0, float& d1, float& d2, float& d3,
                                         uint32_t a0, uint32_t a1, uint32_t a2, uint32_t a3,
                                         uint32_t b0, uint32_t b1) {
    asm volatile(
        "mma.sync.aligned.m16n8k16.row.col.f32.bf16.bf16.f32 "
        "{%0,%1,%2,%3}, {%4,%5,%6,%7}, {%8,%9}, {%0,%1,%2,%3};"
        : "+f"(d0), "+f"(d1), "+f"(d2), "+f"(d3)
        : "r"(a0), "r"(a1), "r"(a2), "r"(a3), "r"(b0), "r"(b1));
}
__device__ __forceinline__ float tanh_fast(float x) {
    float r; asm("tanh.approx.f32 %0, %1;" : "=f"(r) : "f"(x)); return r;
}

// ---------------- A tile fp32 -> bf16 SMEM convert (low register pressure) ----
__device__ __forceinline__ void convert_A(uint32_t* Abw, const float* __restrict__ homo,
                                          int n0t, int tid) {
    #pragma unroll 2
    for (int i = 0; i < 32; i++) {
        int idx = i * THREADS + tid;            // 0..8191
        int r = idx >> 6, f4 = idx & 63;        // GEMM row, float4 idx in row
        int m = r >> 4, j = r & 15;
        float4 v = __ldg((const float4*)(homo + ((size_t)m * NTOT + n0t + j) * DD) + f4);
        *(uint2*)(Abw + r * WSW + f4 * 2) = make_uint2(bf2(v.x, v.y), bf2(v.z, v.w));
    }
}

// ---------------- kernel ----------------
__global__ void __launch_bounds__(THREADS, 1)
hete_attn_kernel(const int* __restrict__ nodes,
                 const float* __restrict__ homo,
                 const float* __restrict__ Wg,
                 const float* __restrict__ bg,
                 const float* __restrict__ outemb,
                 float* __restrict__ outp)
{
    extern __shared__ char smraw[];
    __nv_bfloat16* Wb = (__nv_bfloat16*)smraw;          // [256][264] bf16
    __nv_bfloat16* Ab = Wb + 256 * WS;                  // [128][264] bf16
    float* tg   = (float*)(Ab + 128 * WS);              // [16][260] fp32
    float* bias = tg + 16 * TGS;                        // [256]
    float* tnsq = bias + 256;                           // [16 seg][16 j]
    float* tnrm = tnsq + 256;                           // [16]
    float* redd = tnrm + 16;                            // [2 wn][8 m][16 j]
    float* redn = redd + 256;
    float* cosb = redn + 256;                           // [128]
    float* attb = cosb + 128;                           // [128]

    uint32_t* Wbw = (uint32_t*)Wb;
    uint32_t* Abw = (uint32_t*)Ab;
    const uint32_t tg_sb = smem_u32(tg);

    const int tid  = threadIdx.x;
    const int wid  = tid >> 5;
    const int lane = tid & 31;
    const int wm   = wid & 3;        // M-tile (rows wm*32..+32)
    const int wn   = wid >> 2;       // N-tile (cols wn*128..+128)
    const int g    = lane >> 2;      // 0..7
    const int l3   = lane & 3;       // 0..3
    const int tile0 = blockIdx.x * G;

    // ldmatrix per-lane base addresses (bytes)
    // A (x4 = a0..a3 of one ms): lanes 0-7 rows+0 k+0 | 8-15 rows+8 k+0
    //                            | 16-23 rows+0 k+16B | 24-31 rows+8 k+16B
    const int aRow = wm * 32 + (lane & 7) + ((lane >> 3) & 1) * 8;
    const int aKof = (lane >> 4) * 16;
    const uint32_t aBase0 = smem_u32(Ab) + (uint32_t)aRow * WSB + aKof;       // ms=0
    // B (x4 = b0,b1 of nt even | b0,b1 of nt odd): lanes 0-7 rows+0 k+0
    //   | 8-15 rows+0 k+16B | 16-23 rows+8 k+0 | 24-31 rows+8 k+16B
    const int bRow = wn * 128 + (lane & 7) + ((lane >> 4) & 1) * 8;
    const int bKof = ((lane >> 3) & 1) * 16;
    const uint32_t bBase0 = smem_u32(Wb) + (uint32_t)bRow * WSB + bKof;

    // ---- prologue (once per CTA): bias, W fp32->bf16, A(0) fp32->bf16 ----
    bias[tid] = bg[tid];
    #pragma unroll 2
    for (int i = 0; i < 64; i++) {                       // W: 16384 float4
        int idx = i * THREADS + tid;
        int h = idx >> 6, f4 = idx & 63;
        float4 v = __ldg((const float4*)(Wg + (size_t)h * DD) + f4);
        *(uint2*)(Wbw + h * WSW + f4 * 2) = make_uint2(bf2(v.x, v.y), bf2(v.z, v.w));
    }
    convert_A(Abw, homo, tile0 * TN, tid);
    __syncthreads();

    for (int t = 0; t < G; t++) {
        const int n0t = (tile0 + t) * TN;

        // stage tgt(t) via cp.async (hidden behind mainloop)
        #pragma unroll
        for (int q = 0; q < 4; q++) {
            int i = q * THREADS + tid;
            int j = i >> 6, f4 = i & 63;
            int nd = __ldg(&nodes[n0t + j]);
            cp16(tg_sb + (uint32_t)(j * TGS + f4 * 4) * 4,
                 outemb + (size_t)nd * HH + f4 * 4);
        }
        cp_commit();

        float acc[2][16][4];
        #pragma unroll
        for (int ms = 0; ms < 2; ms++)
            #pragma unroll
            for (int nt = 0; nt < 16; nt++)
                #pragma unroll
                for (int e = 0; e < 4; e++) acc[ms][nt][e] = 0.f;

        // ---- mainloop: 16 x k16 bf16 MMA via ldmatrix, zero syncs ----
        #pragma unroll 2
        for (int ks = 0; ks < 16; ks++) {
            const uint32_t kof = (uint32_t)ks * 32;      // 16 bf16 = 32 B
            uint32_t a[2][4];
            ldsm4(a[0][0], a[0][1], a[0][2], a[0][3], aBase0 + kof);
            ldsm4(a[1][0], a[1][1], a[1][2], a[1][3], aBase0 + 16 * WSB + kof);
            #pragma unroll
            for (int p = 0; p < 8; p++) {                // nt pair
                uint32_t b0, b1, b2, b3;
                ldsm4(b0, b1, b2, b3, bBase0 + (uint32_t)p * 16 * WSB + kof);
                #pragma unroll
                for (int ms = 0; ms < 2; ms++) {
                    mma_bf16(acc[ms][2 * p][0], acc[ms][2 * p][1],
                             acc[ms][2 * p][2], acc[ms][2 * p][3],
                             a[ms][0], a[ms][1], a[ms][2], a[ms][3], b0, b1);
                    mma_bf16(acc[ms][2 * p + 1][0], acc[ms][2 * p + 1][1],
                             acc[ms][2 * p + 1][2], acc[ms][2 * p + 1][3],
                             a[ms][0], a[ms][1], a[ms][2], a[ms][3], b2, b3);
                }
            }
        }
        cp_wait<0>();
        __syncthreads();                                 // tgt ready; all MMA done

        // ---- epilogue ----
        {   // partial ||tgt||^2
            int j = tid >> 4, seg = tid & 15;
            float a0 = 0.f;
            #pragma unroll
            for (int e = 0; e < 16; e++) {
                float v = tg[j * TGS + seg * 16 + e];
                a0 += v * v;
            }
            tnsq[seg * 16 + j] = a0;
        }
        {   // tanh + dot/norm from register accumulators
            float dot[2][2] = {{0.f, 0.f}, {0.f, 0.f}};
            float nrm[2][2] = {{0.f, 0.f}, {0.f, 0.f}};
            #pragma unroll
            for (int nt = 0; nt < 16; nt++) {
                int nc = wn * 128 + nt * 8 + 2 * l3;
                float bias0 = bias[nc];
                float bias1 = bias[nc + 1];
                float t0a = tg[g * TGS + nc];
                float t1a = tg[g * TGS + nc + 1];
                float t0b = tg[(g + 8) * TGS + nc];
                float t1b = tg[(g + 8) * TGS + nc + 1];
                #pragma unroll
                for (int ms = 0; ms < 2; ms++) {
                    float h0 = tanh_fast(acc[ms][nt][0] + bias0);
                    float h1 = tanh_fast(acc[ms][nt][1] + bias1);
                    float h2 = tanh_fast(acc[ms][nt][2] + bias0);
                    float h3 = tanh_fast(acc[ms][nt][3] + bias1);
                    dot[ms][0] += h0 * t0a + h1 * t1a;
                    nrm[ms][0] += h0 * h0 + h1 * h1;
                    dot[ms][1] += h2 * t0b + h3 * t1b;
                    nrm[ms][1] += h2 * h2 + h3 * h3;
                }
            }
            #pragma unroll
            for (int ms = 0; ms < 2; ms++)
                #pragma unroll
                for (int s1 = 0; s1 < 2; s1++) {
                    float d = dot[ms][s1], q = nrm[ms][s1];
                    d += __shfl_xor_sync(0xFFFFFFFF, d, 1);
                    d += __shfl_xor_sync(0xFFFFFFFF, d, 2);
                    q += __shfl_xor_sync(0xFFFFFFFF, q, 1);
                    q += __shfl_xor_sync(0xFFFFFFFF, q, 2);
                    if (l3 == 0) {
                        int m = wm * 2 + ms, j = g + s1 * 8;
                        redd[wn * 128 + m * 16 + j] = d;
                        redn[wn * 128 + m * 16 + j] = q;
                    }
                }
        }
        __syncthreads();

        if (tid < 16) {                                  // finalize ||tgt||
            float sum = 0.f;
            #pragma unroll
            for (int e = 0; e < 16; e++) sum += tnsq[e * 16 + tid];
            tnrm[tid] = fmaxf(sqrtf(sum), 1e-8f);
        }
        if (t + 1 < G)                                   // A(t+1): Ab is dead now
            convert_A(Abw, homo, n0t + TN, tid);
        __syncthreads();

        if (tid < 128) {                                 // cosine per (m, j)
            float d = redd[tid] + redd[128 + tid];
            float q = redn[tid] + redn[128 + tid];
            float hn = fmaxf(sqrtf(q), 1e-8f);
            cosb[tid] = d / (hn * tnrm[tid & 15]);
        }
        __syncthreads();

        if (tid < 16) {                                  // softmax over 8 meta-paths
            float cv[MP], mx = -1e30f;
            #pragma unroll
            for (int m = 0; m < MP; m++) { cv[m] = cosb[m * 16 + tid]; mx = fmaxf(mx, cv[m]); }
            float sum = 0.f;
            #pragma unroll
            for (int m = 0; m < MP; m++) { cv[m] = __expf(cv[m] - mx); sum += cv[m]; }
            float inv = 1.f / sum;
            #pragma unroll
            for (int m = 0; m < MP; m++) attb[m * 16 + tid] = cv[m] * inv;
        }
        __syncthreads();

        {   // final weighted sum: exact fp32, homo re-read (L2-hot)
            int j = tid >> 4, q = tid & 15;              // 16 threads per node
            float a[MP];
            #pragma unroll
            for (int m = 0; m < MP; m++) a[m] = attb[m * 16 + j];
            float4* orow = (float4*)(outp + (size_t)(n0t + j) * DD);
            #pragma unroll
            for (int sQ = 0; sQ < 4; sQ++) {
                int k4 = q + sQ * 16;                    // 0..63
                float4 accv = make_float4(0.f, 0.f, 0.f, 0.f);
                #pragma unroll
                for (int m = 0; m < MP; m++) {
                    float4 v = __ldg((const float4*)(homo +
                               ((size_t)m * NTOT + n0t + j) * DD) + k4);
                    accv.x += a[m] * v.x; accv.y += a[m] * v.y;
                    accv.z += a[m] * v.z; accv.w += a[m] * v.w;
                }
                orow[k4] = accv;
            }
        }
        // next tile's post-mainloop barrier orders all SMEM rewrites (tgt via
        // cp.async is the only pre-barrier write; weighted sum doesn't read tg).
    }
}

// ---------------- launch ----------------
extern "C" void kernel_launch(void* const* d_in, const int* in_sizes, int n_in,
                              void* d_out, int out_size) {
    const int* nodes = nullptr;
    const float *homo = nullptr, *W = nullptr, *b = nullptr, *emb = nullptr;
    for (int i = 0; i < n_in; i++) {
        switch (in_sizes[i]) {
            case 100000:    nodes = (const int*)d_in[i];   break;  // nodes [N]
            case 204800000: homo  = (const float*)d_in[i]; break;  // homo  [M,N,D]
            case 65536:     W     = (const float*)d_in[i]; break;  // W     [H,D]
            case 256:       b     = (const float*)d_in[i]; break;  // b     [H]
            case 51200000:  emb   = (const float*)d_in[i]; break;  // out_embedding
        }
    }
    cudaFuncSetAttribute(hete_attn_kernel,
                         cudaFuncAttributeMaxDynamicSharedMemorySize, SMEM_REQ);
    hete_attn_kernel<<<NTOT / (TN * G), THREADS, SMEM_REQ>>>(nodes, homo, W, b, emb, (float*)d_out);
}